// round 4
// baseline (speedup 1.0000x reference)
#include <cuda_runtime.h>
#include <math.h>

#define NBLK 1184         // 4 CTAs/SM wave structure; measured 33us main loop in R1
#define NTHR 256
#define NCOL 256

// Per-block per-column partial sums of squares (1.2 MB static scratch, L2-resident).
__device__ float g_partials[NBLK * NCOL];
__device__ unsigned int g_count;   // zero at load; last block resets each call

__global__ void __launch_bounds__(NTHR, 4)
colsq_fused_kernel(const float* __restrict__ d, long long n_f4,
                   float* __restrict__ out) {
    const int tid = threadIdx.x;
    const float4* __restrict__ p = (const float4*)d;

    // Stride in floats = gridDim*NTHR*4, a multiple of 256, so every thread
    // touches a fixed 4-column group.
    long long idx = (long long)blockIdx.x * NTHR + tid;
    const long long stride = (long long)gridDim.x * NTHR;

    float a0 = 0.f, a1 = 0.f, a2 = 0.f, a3 = 0.f;

    // Unroll x4 (1184 blocks -> ~55 f4 per thread; x4 keeps MLP high, regs low).
    long long i = idx;
    for (; i + 3 * stride < n_f4; i += 4 * stride) {
        float4 v0 = p[i];
        float4 v1 = p[i + stride];
        float4 v2 = p[i + 2 * stride];
        float4 v3 = p[i + 3 * stride];
        a0 += v0.x * v0.x; a1 += v0.y * v0.y; a2 += v0.z * v0.z; a3 += v0.w * v0.w;
        a0 += v1.x * v1.x; a1 += v1.y * v1.y; a2 += v1.z * v1.z; a3 += v1.w * v1.w;
        a0 += v2.x * v2.x; a1 += v2.y * v2.y; a2 += v2.z * v2.z; a3 += v2.w * v2.w;
        a0 += v3.x * v3.x; a1 += v3.y * v3.y; a2 += v3.z * v3.z; a3 += v3.w * v3.w;
    }
    for (; i < n_f4; i += stride) {
        float4 v = p[i];
        a0 += v.x * v.x; a1 += v.y * v.y; a2 += v.z * v.z; a3 += v.w * v.w;
    }

    // Deterministic block reduction: 4 replicas of the 256-column vector.
    __shared__ float s[4][NCOL];
    const int c = (tid * 4) & (NCOL - 1);
    const int rep = tid >> 6;  // 0..3
    s[rep][c + 0] = a0;
    s[rep][c + 1] = a1;
    s[rep][c + 2] = a2;
    s[rep][c + 3] = a3;
    __syncthreads();

    float part = s[0][tid] + s[1][tid] + s[2][tid] + s[3][tid];
    g_partials[blockIdx.x * NCOL + tid] = part;

    // --- last-block-done reduction ---
    __shared__ bool isLast;
    __threadfence();                       // partial visible before count bump
    if (tid == 0) {
        unsigned int old = atomicAdd(&g_count, 1u);
        isLast = (old == (unsigned)(gridDim.x - 1));
    }
    __syncthreads();
    if (!isLast) return;

    __threadfence();                       // acquire side

    // Epilogue: 1184x256 floats = 1.2 MB, L2-hot. Read as float4:
    // thread tid handles quad q = tid&63 (cols 4q..4q+3), replica r = tid>>6
    // sums blocks b = r, r+4, r+8, ... (296 each), unrolled x4 for MLP.
    const float4* __restrict__ gp4 = (const float4*)g_partials;  // [NBLK][64]
    const int q = tid & 63;
    const int r = tid >> 6;

    float4 acc0 = make_float4(0.f, 0.f, 0.f, 0.f);
    float4 acc1 = make_float4(0.f, 0.f, 0.f, 0.f);
    float4 acc2 = make_float4(0.f, 0.f, 0.f, 0.f);
    float4 acc3 = make_float4(0.f, 0.f, 0.f, 0.f);
    int b = r;
    for (; b + 12 < NBLK; b += 16) {
        float4 v0 = __ldcg(&gp4[(b     ) * 64 + q]);
        float4 v1 = __ldcg(&gp4[(b +  4) * 64 + q]);
        float4 v2 = __ldcg(&gp4[(b +  8) * 64 + q]);
        float4 v3 = __ldcg(&gp4[(b + 12) * 64 + q]);
        acc0.x += v0.x; acc0.y += v0.y; acc0.z += v0.z; acc0.w += v0.w;
        acc1.x += v1.x; acc1.y += v1.y; acc1.z += v1.z; acc1.w += v1.w;
        acc2.x += v2.x; acc2.y += v2.y; acc2.z += v2.z; acc2.w += v2.w;
        acc3.x += v3.x; acc3.y += v3.y; acc3.z += v3.z; acc3.w += v3.w;
    }
    for (; b < NBLK; b += 4) {
        float4 v = __ldcg(&gp4[b * 64 + q]);
        acc0.x += v.x; acc0.y += v.y; acc0.z += v.z; acc0.w += v.w;
    }
    float4 acc;
    acc.x = (acc0.x + acc1.x) + (acc2.x + acc3.x);
    acc.y = (acc0.y + acc1.y) + (acc2.y + acc3.y);
    acc.z = (acc0.z + acc1.z) + (acc2.z + acc3.z);
    acc.w = (acc0.w + acc1.w) + (acc2.w + acc3.w);

    // Combine 4 replicas in smem, then (x-1)^2 and tree-reduce.
    __shared__ float4 sm4[4][64];
    sm4[r][q] = acc;
    __syncthreads();

    __shared__ float red[64];
    if (tid < 64) {
        float4 t0 = sm4[0][tid], t1 = sm4[1][tid], t2 = sm4[2][tid], t3 = sm4[3][tid];
        float cx = (t0.x + t1.x) + (t2.x + t3.x) - 1.0f;
        float cy = (t0.y + t1.y) + (t2.y + t3.y) - 1.0f;
        float cz = (t0.z + t1.z) + (t2.z + t3.z) - 1.0f;
        float cw = (t0.w + t1.w) + (t2.w + t3.w) - 1.0f;
        red[tid] = (cx * cx + cy * cy) + (cz * cz + cw * cw);
    }
    __syncthreads();

    if (tid < 32) {
        float v = red[tid] + red[tid + 32];
        #pragma unroll
        for (int off = 16; off > 0; off >>= 1)
            v += __shfl_down_sync(0xFFFFFFFF, v, off);
        if (tid == 0) {
            out[0] = 0.001f * sqrtf(v);
            g_count = 0;                   // reset for next graph replay
        }
    }
}

extern "C" void kernel_launch(void* const* d_in, const int* in_sizes, int n_in,
                              void* d_out, int out_size) {
    const float* d = (const float*)d_in[0];
    float* out = (float*)d_out;
    long long n = (long long)in_sizes[0];      // 262144 * 256
    long long n_f4 = n / 4;

    colsq_fused_kernel<<<NBLK, NTHR>>>(d, n_f4, out);
}

// round 7
// speedup vs baseline: 2.0188x; 2.0188x over previous
#include <cuda_runtime.h>
#include <math.h>

#define NBLK 608          // 4 CTAs/SM x 152 SMs on GB300: one full wave, 32 warps/SM
#define NTHR 256
#define NCOL 256

// Per-block per-column partial sums of squares (623 KB static scratch).
// float4-typed so vectorized epilogue loads are 16B-aligned.
__device__ float4 g_partials4[NBLK * NCOL / 4];   // [NBLK][64] float4 == [NBLK][256] float

__global__ void __launch_bounds__(NTHR, 4)
colsq_kernel(const float* __restrict__ d, long long n_f4) {
    const int tid = threadIdx.x;
    const float4* __restrict__ p = (const float4*)d;

    // Stride in floats = gridDim*NTHR*4, a multiple of 256, so every thread
    // touches a fixed 4-column group.
    long long idx = (long long)blockIdx.x * NTHR + tid;
    const long long stride = (long long)gridDim.x * NTHR;

    float a0 = 0.f, a1 = 0.f, a2 = 0.f, a3 = 0.f;

    // Unroll x8: 8 independent LDG.128 in flight per thread.
    long long i = idx;
    for (; i + 7 * stride < n_f4; i += 8 * stride) {
        float4 v0 = p[i];
        float4 v1 = p[i + stride];
        float4 v2 = p[i + 2 * stride];
        float4 v3 = p[i + 3 * stride];
        float4 v4 = p[i + 4 * stride];
        float4 v5 = p[i + 5 * stride];
        float4 v6 = p[i + 6 * stride];
        float4 v7 = p[i + 7 * stride];
        a0 += v0.x * v0.x; a1 += v0.y * v0.y; a2 += v0.z * v0.z; a3 += v0.w * v0.w;
        a0 += v1.x * v1.x; a1 += v1.y * v1.y; a2 += v1.z * v1.z; a3 += v1.w * v1.w;
        a0 += v2.x * v2.x; a1 += v2.y * v2.y; a2 += v2.z * v2.z; a3 += v2.w * v2.w;
        a0 += v3.x * v3.x; a1 += v3.y * v3.y; a2 += v3.z * v3.z; a3 += v3.w * v3.w;
        a0 += v4.x * v4.x; a1 += v4.y * v4.y; a2 += v4.z * v4.z; a3 += v4.w * v4.w;
        a0 += v5.x * v5.x; a1 += v5.y * v5.y; a2 += v5.z * v5.z; a3 += v5.w * v5.w;
        a0 += v6.x * v6.x; a1 += v6.y * v6.y; a2 += v6.z * v6.z; a3 += v6.w * v6.w;
        a0 += v7.x * v7.x; a1 += v7.y * v7.y; a2 += v7.z * v7.z; a3 += v7.w * v7.w;
    }
    for (; i < n_f4; i += stride) {
        float4 v = p[i];
        a0 += v.x * v.x; a1 += v.y * v.y; a2 += v.z * v.z; a3 += v.w * v.w;
    }

    // Deterministic block reduction: 4 replicas of the 256-column vector.
    __shared__ float s[4][NCOL];
    const int c = (tid * 4) & (NCOL - 1);
    const int rep = tid >> 6;  // 0..3 (256 threads)
    s[rep][c + 0] = a0;
    s[rep][c + 1] = a1;
    s[rep][c + 2] = a2;
    s[rep][c + 3] = a3;
    __syncthreads();

    float part = s[0][tid] + s[1][tid] + s[2][tid] + s[3][tid];
    ((float*)g_partials4)[blockIdx.x * NCOL + tid] = part;
}

// One block, 1024 threads, float4 reads with MLP.
// Thread layout: q = tid & 63 -> columns 4q..4q+3; r = tid >> 6 -> replica 0..15.
// Replica r sums rows b = r, r+16, ... (NBLK/16 = 38 rows), unrolled x4.
__global__ void __launch_bounds__(1024)
finalize_kernel(float* __restrict__ out) {
    const int tid = threadIdx.x;
    const int q = tid & 63;
    const int r = tid >> 6;          // 0..15

    const float4* __restrict__ gp4 = g_partials4;  // [NBLK][64]

    float4 acc0 = make_float4(0.f, 0.f, 0.f, 0.f);
    float4 acc1 = make_float4(0.f, 0.f, 0.f, 0.f);
    float4 acc2 = make_float4(0.f, 0.f, 0.f, 0.f);
    float4 acc3 = make_float4(0.f, 0.f, 0.f, 0.f);

    int b = r;
    for (; b + 48 < NBLK; b += 64) {
        float4 v0 = __ldcg(&gp4[(b     ) * 64 + q]);
        float4 v1 = __ldcg(&gp4[(b + 16) * 64 + q]);
        float4 v2 = __ldcg(&gp4[(b + 32) * 64 + q]);
        float4 v3 = __ldcg(&gp4[(b + 48) * 64 + q]);
        acc0.x += v0.x; acc0.y += v0.y; acc0.z += v0.z; acc0.w += v0.w;
        acc1.x += v1.x; acc1.y += v1.y; acc1.z += v1.z; acc1.w += v1.w;
        acc2.x += v2.x; acc2.y += v2.y; acc2.z += v2.z; acc2.w += v2.w;
        acc3.x += v3.x; acc3.y += v3.y; acc3.z += v3.z; acc3.w += v3.w;
    }
    for (; b < NBLK; b += 16) {
        float4 v = __ldcg(&gp4[b * 64 + q]);
        acc0.x += v.x; acc0.y += v.y; acc0.z += v.z; acc0.w += v.w;
    }
    float4 acc;
    acc.x = (acc0.x + acc1.x) + (acc2.x + acc3.x);
    acc.y = (acc0.y + acc1.y) + (acc2.y + acc3.y);
    acc.z = (acc0.z + acc1.z) + (acc2.z + acc3.z);
    acc.w = (acc0.w + acc1.w) + (acc2.w + acc3.w);

    // Combine 16 replicas in smem, then (x-1)^2 and tree-reduce 64 -> 1.
    __shared__ float4 sm4[16][64];
    sm4[r][q] = acc;
    __syncthreads();

    __shared__ float red[64];
    if (tid < 64) {
        float4 t = sm4[0][tid];
        #pragma unroll
        for (int k = 1; k < 16; k++) {
            float4 u = sm4[k][tid];
            t.x += u.x; t.y += u.y; t.z += u.z; t.w += u.w;
        }
        float cx = t.x - 1.0f;
        float cy = t.y - 1.0f;
        float cz = t.z - 1.0f;
        float cw = t.w - 1.0f;
        red[tid] = (cx * cx + cy * cy) + (cz * cz + cw * cw);
    }
    __syncthreads();

    if (tid < 32) {
        float v = red[tid] + red[tid + 32];
        #pragma unroll
        for (int off = 16; off > 0; off >>= 1)
            v += __shfl_down_sync(0xFFFFFFFF, v, off);
        if (tid == 0) out[0] = 0.001f * sqrtf(v);
    }
}

extern "C" void kernel_launch(void* const* d_in, const int* in_sizes, int n_in,
                              void* d_out, int out_size) {
    const float* d = (const float*)d_in[0];
    float* out = (float*)d_out;
    long long n = (long long)in_sizes[0];      // 262144 * 256
    long long n_f4 = n / 4;

    colsq_kernel<<<NBLK, NTHR>>>(d, n_f4);
    finalize_kernel<<<1, 1024>>>(out);
}